// round 1
// baseline (speedup 1.0000x reference)
#include <cuda_runtime.h>
#include <math.h>

// Problem constants
#define L_     128
#define CTX_   896
#define T_     1024
#define STATE_ 3072
#define S_     4096
#define HID_   4096
#define HQ_    32
#define HKV_   8
#define REP_   4
#define D_     128
#define HALF_  64
#define EPS_   1e-6f
#define SCALE_ 0.08838834764831845f   // 128^-0.5

// GEMM tiling
#define BM 64
#define BN 64
#define BK 16

// ---------------- device scratch (no allocations allowed) ----------------
__device__ float g_c[T_ * HID_];            // concat(x_ctx, x)           16 MB
__device__ float g_q[L_ * HQ_ * D_];        // raw q projection            2 MB
__device__ float g_qf[HQ_ * L_ * D_];       // normed+roped q (H,L,D)      2 MB
__device__ float g_kraw[T_ * HKV_ * D_];    // raw k projection            4 MB
__device__ float g_vraw[T_ * HKV_ * D_];    // raw v projection            4 MB
__device__ float g_scores[(size_t)HQ_ * L_ * S_]; // scores / probs       64 MB
__device__ float g_o[L_ * HQ_ * D_];        // attention output (L,HQ*D)   2 MB

// ---------------- concat c = [x_ctx; x] ----------------
__global__ void __launch_bounds__(256) concat_c(
    const float* __restrict__ xc, const float* __restrict__ x, float* __restrict__ c) {
  int i = blockIdx.x * 256 + threadIdx.x;     // float4 index, total T_*HID_/4
  const int CV = CTX_ * HID_ / 4;
  float4 v = (i < CV) ? ((const float4*)xc)[i] : ((const float4*)x)[i - CV];
  ((float4*)c)[i] = v;
}

// ---------------- generic SGEMM: C[M][N] = A[M][K] * B[N][K]^T ----------------
__global__ void __launch_bounds__(256) sgemm_abT(
    const float* __restrict__ A, const float* __restrict__ B, float* __restrict__ C,
    int K, int lda, int ldb, int ldc) {
  __shared__ float As[BK][BM + 4];
  __shared__ float Bs[BK][BN + 4];
  const int tid = threadIdx.x;
  const int tx = tid & 15, ty = tid >> 4;
  const int m0 = blockIdx.y * BM, n0 = blockIdx.x * BN;
  const int lrow = tid >> 2;           // 0..63
  const int lcol = (tid & 3) << 2;     // 0,4,8,12
  const float* Ag = A + (size_t)(m0 + lrow) * lda + lcol;
  const float* Bg = B + (size_t)(n0 + lrow) * ldb + lcol;
  float acc[4][4] = {};
  for (int k0 = 0; k0 < K; k0 += BK) {
    float4 av = *(const float4*)(Ag + k0);
    float4 bv = *(const float4*)(Bg + k0);
    As[lcol + 0][lrow] = av.x; As[lcol + 1][lrow] = av.y;
    As[lcol + 2][lrow] = av.z; As[lcol + 3][lrow] = av.w;
    Bs[lcol + 0][lrow] = bv.x; Bs[lcol + 1][lrow] = bv.y;
    Bs[lcol + 2][lrow] = bv.z; Bs[lcol + 3][lrow] = bv.w;
    __syncthreads();
#pragma unroll
    for (int kk = 0; kk < BK; kk++) {
      float4 a = *(const float4*)&As[kk][ty << 2];
      float4 b = *(const float4*)&Bs[kk][tx << 2];
      float ar[4] = {a.x, a.y, a.z, a.w};
      float br[4] = {b.x, b.y, b.z, b.w};
#pragma unroll
      for (int i = 0; i < 4; i++)
#pragma unroll
        for (int j = 0; j < 4; j++) acc[i][j] += ar[i] * br[j];
    }
    __syncthreads();
  }
#pragma unroll
  for (int i = 0; i < 4; i++) {
    float4 r = make_float4(acc[i][0], acc[i][1], acc[i][2], acc[i][3]);
    *(float4*)(C + (size_t)(m0 + (ty << 2) + i) * ldc + n0 + (tx << 2)) = r;
  }
}

// ---------------- fused ane-norm + RoPE (one warp per row of D=128) ----------------
// src layout: [row][head] packed rows of D  (row index r = row*NH + head)
// dst layout: [head][row][D]
__global__ void __launch_bounds__(128) norm_rope(
    const float* __restrict__ src, const float* __restrict__ w,
    const float* __restrict__ cs, const float* __restrict__ sn,
    float* __restrict__ dst, int NH, int NR) {
  int r = blockIdx.x * 4 + (threadIdx.x >> 5);
  int lane = threadIdx.x & 31;
  int row = r / NH, h = r - row * NH;
  float4 v = ((const float4*)(src + (size_t)r * D_))[lane];
  float s = v.x + v.y + v.z + v.w;
#pragma unroll
  for (int o = 16; o; o >>= 1) s += __shfl_xor_sync(0xffffffffu, s, o);
  float mean = s * (1.0f / D_);
  float4 c = make_float4(v.x - mean, v.y - mean, v.z - mean, v.w - mean);
  float q2 = c.x * c.x + c.y * c.y + c.z * c.z + c.w * c.w;
#pragma unroll
  for (int o = 16; o; o >>= 1) q2 += __shfl_xor_sync(0xffffffffu, q2, o);
  float inv = rsqrtf(q2 * (1.0f / D_) + EPS_);
  float4 wv = ((const float4*)w)[lane];
  float4 n = make_float4(c.x * inv * wv.x, c.y * inv * wv.y,
                         c.z * inv * wv.z, c.w * inv * wv.w);
  // rope: partner lane holds the other half (HALF_=64 -> lane xor 16)
  float4 p;
  p.x = __shfl_xor_sync(0xffffffffu, n.x, 16);
  p.y = __shfl_xor_sync(0xffffffffu, n.y, 16);
  p.z = __shfl_xor_sync(0xffffffffu, n.z, 16);
  p.w = __shfl_xor_sync(0xffffffffu, n.w, 16);
  float sg = (lane < 16) ? -1.0f : 1.0f;
  float4 co = ((const float4*)(cs + (size_t)row * D_))[lane];
  float4 si = ((const float4*)(sn + (size_t)row * D_))[lane];
  float4 o;
  o.x = n.x * co.x + sg * p.x * si.x;
  o.y = n.y * co.y + sg * p.y * si.y;
  o.z = n.z * co.z + sg * p.z * si.z;
  o.w = n.w * co.w + sg * p.w * si.w;
  ((float4*)(dst + ((size_t)h * NR + row) * D_))[lane] = o;
}

// ---------------- v transpose (t,h,d) -> (h,t,d) ----------------
__global__ void __launch_bounds__(256) vtrans(
    const float* __restrict__ src, float* __restrict__ dst) {
  int i = blockIdx.x * 256 + threadIdx.x;   // float4 index, total 262144
  int d4 = i & 31;
  int h = (i >> 5) & 7;
  int t = i >> 8;
  ((float4*)dst)[((size_t)h * T_ + t) * 32 + d4] = ((const float4*)src)[i];
}

// ---------------- scores = q @ K^T (batched over q-heads, split K source) ----------------
__global__ void __launch_bounds__(256) attn_scores(
    const float* __restrict__ Q,   // [HQ][L][D]
    const float* __restrict__ Kc,  // [HKV][STATE][D]
    const float* __restrict__ Kn,  // [HKV][T][D]
    float* __restrict__ Sc) {      // [HQ][L][S]
  const int hq = blockIdx.z;
  const int g = hq >> 2;  // REP=4
  __shared__ float As[BK][BM + 4];
  __shared__ float Bs[BK][BN + 4];
  const int tid = threadIdx.x;
  const int tx = tid & 15, ty = tid >> 4;
  const int m0 = blockIdx.y * BM, n0 = blockIdx.x * BN;
  const int lrow = tid >> 2;
  const int lcol = (tid & 3) << 2;
  const float* Ag = Q + (size_t)hq * L_ * D_ + (size_t)(m0 + lrow) * D_ + lcol;
  const int s = n0 + lrow;
  const float* Bg = (s < STATE_)
      ? Kc + ((size_t)g * STATE_ + s) * D_ + lcol
      : Kn + ((size_t)g * T_ + (s - STATE_)) * D_ + lcol;
  float acc[4][4] = {};
  for (int k0 = 0; k0 < D_; k0 += BK) {
    float4 av = *(const float4*)(Ag + k0);
    float4 bv = *(const float4*)(Bg + k0);
    As[lcol + 0][lrow] = av.x; As[lcol + 1][lrow] = av.y;
    As[lcol + 2][lrow] = av.z; As[lcol + 3][lrow] = av.w;
    Bs[lcol + 0][lrow] = bv.x; Bs[lcol + 1][lrow] = bv.y;
    Bs[lcol + 2][lrow] = bv.z; Bs[lcol + 3][lrow] = bv.w;
    __syncthreads();
#pragma unroll
    for (int kk = 0; kk < BK; kk++) {
      float4 a = *(const float4*)&As[kk][ty << 2];
      float4 b = *(const float4*)&Bs[kk][tx << 2];
      float ar[4] = {a.x, a.y, a.z, a.w};
      float br[4] = {b.x, b.y, b.z, b.w};
#pragma unroll
      for (int i = 0; i < 4; i++)
#pragma unroll
        for (int j = 0; j < 4; j++) acc[i][j] += ar[i] * br[j];
    }
    __syncthreads();
  }
  float* Cb = Sc + (size_t)hq * L_ * S_;
#pragma unroll
  for (int i = 0; i < 4; i++) {
    float4 r = make_float4(acc[i][0], acc[i][1], acc[i][2], acc[i][3]);
    *(float4*)(Cb + (size_t)(m0 + (ty << 2) + i) * S_ + n0 + (tx << 2)) = r;
  }
}

// ---------------- masked scaled softmax over S (one block per (hq,l) row) ----------------
__global__ void __launch_bounds__(256) softmax_mask(float* __restrict__ Sc) {
  const int rid = blockIdx.x;            // hq*L + l
  const int l = rid & (L_ - 1);
  const int allowed = STATE_ + CTX_ + l + 1;
  float* row = Sc + (size_t)rid * S_;
  const int t = threadIdx.x;
  float v[16];
  float mx = -INFINITY;
#pragma unroll
  for (int i = 0; i < 16; i++) {
    int idx = t + 256 * i;
    float x = (idx < allowed) ? row[idx] * SCALE_ : -INFINITY;
    v[i] = x;
    mx = fmaxf(mx, x);
  }
  __shared__ float red[8];
  int lane = t & 31, wid = t >> 5;
#pragma unroll
  for (int o = 16; o; o >>= 1) mx = fmaxf(mx, __shfl_xor_sync(0xffffffffu, mx, o));
  if (lane == 0) red[wid] = mx;
  __syncthreads();
  mx = red[0];
#pragma unroll
  for (int wi = 1; wi < 8; wi++) mx = fmaxf(mx, red[wi]);
  __syncthreads();
  float sum = 0.f;
#pragma unroll
  for (int i = 0; i < 16; i++) {
    float e = (v[i] > -INFINITY) ? __expf(v[i] - mx) : 0.f;
    v[i] = e;
    sum += e;
  }
#pragma unroll
  for (int o = 16; o; o >>= 1) sum += __shfl_xor_sync(0xffffffffu, sum, o);
  if (lane == 0) red[wid] = sum;
  __syncthreads();
  sum = red[0] + red[1] + red[2] + red[3] + red[4] + red[5] + red[6] + red[7];
  float inv = 1.f / sum;
#pragma unroll
  for (int i = 0; i < 16; i++) row[t + 256 * i] = v[i] * inv;
}

// ---------------- O = P @ V (batched over q-heads, split V source) ----------------
__global__ void __launch_bounds__(256) attn_pv(
    const float* __restrict__ P,   // [HQ][L][S]
    const float* __restrict__ Vc,  // [HKV][STATE][D]
    const float* __restrict__ Vn,  // [HKV][T][D]
    float* __restrict__ O) {       // [L][HQ*D]
  const int hq = blockIdx.z;
  const int g = hq >> 2;
  __shared__ float As[BK][BM + 4];
  __shared__ float Bs[BK][BN + 4];
  const int tid = threadIdx.x;
  const int tx = tid & 15, ty = tid >> 4;
  const int m0 = blockIdx.y * BM, n0 = blockIdx.x * BN;
  const int alrow = tid >> 2;
  const int alcol = (tid & 3) << 2;
  const float* Ag = P + (size_t)hq * L_ * S_ + (size_t)(m0 + alrow) * S_ + alcol;
  const int bkrow = tid >> 4;           // 0..15
  const int bncol = (tid & 15) << 2;    // 0..60
  float acc[4][4] = {};
  for (int k0 = 0; k0 < S_; k0 += BK) {
    float4 av = *(const float4*)(Ag + k0);
    int s = k0 + bkrow;
    const float* brow = (s < STATE_)
        ? Vc + ((size_t)g * STATE_ + s) * D_
        : Vn + ((size_t)g * T_ + (s - STATE_)) * D_;
    float4 bv = *(const float4*)(brow + n0 + bncol);
    As[alcol + 0][alrow] = av.x; As[alcol + 1][alrow] = av.y;
    As[alcol + 2][alrow] = av.z; As[alcol + 3][alrow] = av.w;
    *(float4*)&Bs[bkrow][bncol] = bv;
    __syncthreads();
#pragma unroll
    for (int kk = 0; kk < BK; kk++) {
      float4 a = *(const float4*)&As[kk][ty << 2];
      float4 b = *(const float4*)&Bs[kk][tx << 2];
      float ar[4] = {a.x, a.y, a.z, a.w};
      float br[4] = {b.x, b.y, b.z, b.w};
#pragma unroll
      for (int i = 0; i < 4; i++)
#pragma unroll
        for (int j = 0; j < 4; j++) acc[i][j] += ar[i] * br[j];
    }
    __syncthreads();
  }
  float* Cb = O + (size_t)hq * D_;
#pragma unroll
  for (int i = 0; i < 4; i++) {
    float4 r = make_float4(acc[i][0], acc[i][1], acc[i][2], acc[i][3]);
    *(float4*)(Cb + (size_t)(m0 + (ty << 2) + i) * (HQ_ * D_) + n0 + (tx << 2)) = r;
  }
}

// ---------------- host launcher ----------------
extern "C" void kernel_launch(void* const* d_in, const int* in_sizes, int n_in,
                              void* d_out, int out_size) {
  const float* x    = (const float*)d_in[0];
  const float* xctx = (const float*)d_in[1];
  const float* cosq = (const float*)d_in[2];
  const float* sinq = (const float*)d_in[3];
  const float* cosk = (const float*)d_in[4];
  const float* sink = (const float*)d_in[5];
  const float* cK   = (const float*)d_in[6];
  const float* cV   = (const float*)d_in[7];
  // d_in[8] = causal_mask (bool) -- handled analytically
  const float* Wq   = (const float*)d_in[9];
  const float* Wk   = (const float*)d_in[10];
  const float* Wv   = (const float*)d_in[11];
  const float* Wo   = (const float*)d_in[12];
  const float* qw   = (const float*)d_in[13];
  const float* kw   = (const float*)d_in[14];

  float* out   = (float*)d_out;
  float* k_out = out + (size_t)L_ * HID_;                 // (HKV, T, D)
  float* v_out = k_out + (size_t)HKV_ * T_ * D_;          // (HKV, T, D)

  float *pc, *pq, *pqf, *pkraw, *pvraw, *psc, *po;
  cudaGetSymbolAddress((void**)&pc, g_c);
  cudaGetSymbolAddress((void**)&pq, g_q);
  cudaGetSymbolAddress((void**)&pqf, g_qf);
  cudaGetSymbolAddress((void**)&pkraw, g_kraw);
  cudaGetSymbolAddress((void**)&pvraw, g_vraw);
  cudaGetSymbolAddress((void**)&psc, g_scores);
  cudaGetSymbolAddress((void**)&po, g_o);

  // 1. c = [x_ctx; x]
  concat_c<<<T_ * HID_ / 4 / 256, 256>>>(xctx, x, pc);
  // 2. projections
  sgemm_abT<<<dim3(HID_ / BN, L_ / BM), 256>>>(x, Wq, pq, HID_, HID_, HID_, HID_);
  sgemm_abT<<<dim3(HKV_ * D_ / BN, T_ / BM), 256>>>(pc, Wk, pkraw, HID_, HID_, HID_, HKV_ * D_);
  sgemm_abT<<<dim3(HKV_ * D_ / BN, T_ / BM), 256>>>(pc, Wv, pvraw, HID_, HID_, HID_, HKV_ * D_);
  // 3. norm + rope
  norm_rope<<<(L_ * HQ_) / 4, 128>>>(pq, qw, cosq, sinq, pqf, HQ_, L_);
  norm_rope<<<(T_ * HKV_) / 4, 128>>>(pkraw, kw, cosk, sink, k_out, HKV_, T_);
  vtrans<<<T_ * HKV_ * D_ / 4 / 256, 256>>>(pvraw, v_out);
  // 4. attention
  attn_scores<<<dim3(S_ / BN, L_ / BM, HQ_), 256>>>(pqf, cK, k_out, psc);
  softmax_mask<<<HQ_ * L_, 256>>>(psc);
  attn_pv<<<dim3(D_ / BN, L_ / BM, HQ_), 256>>>(psc, cV, v_out, po);
  // 5. output projection (writes d_out[0 : L*HID])
  sgemm_abT<<<dim3(HID_ / BN, L_ / BM), 256>>>(po, Wo, out, HQ_ * D_, HQ_ * D_, HQ_ * D_, HID_);

  (void)in_sizes; (void)n_in; (void)out_size;
}

// round 2
// speedup vs baseline: 1.9615x; 1.9615x over previous
#include <cuda_runtime.h>
#include <cuda_bf16.h>
#include <math.h>
#include <stdint.h>

// Problem constants
#define L_     128
#define CTX_   896
#define T_     1024
#define STATE_ 3072
#define S_     4096
#define HID_   4096
#define HQ_    32
#define HKV_   8
#define D_     128
#define EPS_   1e-6f
#define SCALE_ 0.08838834764831845f   // 128^-0.5

#define GSTR   40                      // bf16 smem row stride (halves): 80B, 16B-aligned, conflict-free
#define SMEM_BYTES (2*2048*4 /*A f32*/ + 2*2048*4 /*B f32*/ + 4*64*GSTR*2 /*bf16 tiles*/)

// ---------------- device scratch ----------------
__device__ float g_c[T_ * HID_];                 // concat(x_ctx, x)
__device__ float g_q[L_ * HQ_ * D_];             // raw q projection
__device__ float g_qf[HQ_ * L_ * D_];            // normed+roped q (H,L,D)
__device__ float g_kraw[T_ * HKV_ * D_];         // raw k projection
__device__ float g_vraw[T_ * HKV_ * D_];         // raw v projection
__device__ float g_kfull[HKV_ * S_ * D_];        // full K (cache+new) (H,S,D)
__device__ float g_vt[HKV_ * D_ * S_];           // full V transposed (H,D,S)
__device__ float g_scores[(size_t)HQ_ * L_ * S_];// scores / probs
__device__ float g_o[L_ * HQ_ * D_];             // attention output (L, HQ*D)

// ---------------- small helpers ----------------
__device__ __forceinline__ void cp_async16(uint32_t saddr, const void* g) {
  asm volatile("cp.async.cg.shared.global [%0], [%1], 16;\n" :: "r"(saddr), "l"(g));
}
__device__ __forceinline__ void cp_commit() { asm volatile("cp.async.commit_group;\n"); }
__device__ __forceinline__ void cp_wait0()  { asm volatile("cp.async.wait_group 0;\n"); }
__device__ __forceinline__ void ldm_x4(uint32_t (&r)[4], uint32_t addr) {
  asm volatile("ldmatrix.sync.aligned.m8n8.x4.shared.b16 {%0,%1,%2,%3}, [%4];\n"
    : "=r"(r[0]), "=r"(r[1]), "=r"(r[2]), "=r"(r[3]) : "r"(addr));
}
__device__ __forceinline__ void mma16816(float (&d)[4], const uint32_t (&a)[4],
                                         uint32_t b0, uint32_t b1) {
  asm volatile("mma.sync.aligned.m16n8k16.row.col.f32.bf16.bf16.f32 "
    "{%0,%1,%2,%3},{%4,%5,%6,%7},{%8,%9},{%0,%1,%2,%3};\n"
    : "+f"(d[0]), "+f"(d[1]), "+f"(d[2]), "+f"(d[3])
    : "r"(a[0]), "r"(a[1]), "r"(a[2]), "r"(a[3]), "r"(b0), "r"(b1));
}

// ---------------- concat c = [x_ctx; x] ----------------
__global__ void __launch_bounds__(256) concat_c(
    const float* __restrict__ xc, const float* __restrict__ x, float* __restrict__ c) {
  int i = blockIdx.x * 256 + threadIdx.x;
  const int CV = CTX_ * HID_ / 4;
  float4 v = (i < CV) ? ((const float4*)xc)[i] : ((const float4*)x)[i - CV];
  ((float4*)c)[i] = v;
}

// ============ generic batched split-bf16 tensor-core GEMM ============
// C[z][M][N] = A[z][M][K] * B[z>>bshift][N][K]^T   (fp32 in, fp32 out, ~fp32 accuracy)
__global__ void __launch_bounds__(128) gemm_split(
    const float* __restrict__ A, int lda, long long batchA,
    const float* __restrict__ B, int ldb, long long batchB, int bshift,
    float* __restrict__ C, int ldc, long long batchC, int K)
{
  extern __shared__ char smem_raw[];
  float* sA = (float*)smem_raw;                // [2][2048]
  float* sB = sA + 4096;                       // [2][2048]
  __nv_bfloat16* aHi = (__nv_bfloat16*)(sB + 4096);
  __nv_bfloat16* aLo = aHi + 64 * GSTR;
  __nv_bfloat16* bHi = aLo + 64 * GSTR;
  __nv_bfloat16* bLo = bHi + 64 * GSTR;

  const int tid = threadIdx.x, lane = tid & 31, wid = tid >> 5;
  const int wm = wid >> 1, wn = wid & 1;       // 2x2 warp grid, 32x32 per warp
  const int m0 = blockIdx.y * 64, n0 = blockIdx.x * 64;
  const int z = blockIdx.z;
  const float* Ab = A + (long long)z * batchA;
  const float* Bb = B + (long long)(z >> bshift) * batchB;
  float* Cb = C + (long long)z * batchC;

  float acc[2][4][4];
#pragma unroll
  for (int i = 0; i < 2; i++)
#pragma unroll
    for (int j = 0; j < 4; j++)
#pragma unroll
      for (int q = 0; q < 4; q++) acc[i][j][q] = 0.f;

  uint32_t sA32 = (uint32_t)__cvta_generic_to_shared(sA);
  uint32_t sB32 = (uint32_t)__cvta_generic_to_shared(sB);
  uint32_t aHiB = (uint32_t)__cvta_generic_to_shared(aHi);
  uint32_t aLoB = (uint32_t)__cvta_generic_to_shared(aLo);
  uint32_t bHiB = (uint32_t)__cvta_generic_to_shared(bHi);
  uint32_t bLoB = (uint32_t)__cvta_generic_to_shared(bLo);

  // ldmatrix lane address components
  const int a_r = lane & 15;                   // row within 16-row a-tile
  const int a_c = (lane & 16) >> 1;            // 0 or 8 (k-octet)
  const int b_r = (lane & 7) | ((lane & 16) >> 1); // n row (0..15)
  const int b_c = lane & 8;                    // 0 or 8 (k-octet)

  const int iters = K >> 5;
  // prologue: stage 0
  {
#pragma unroll
    for (int j = 0; j < 4; j++) {
      int cc = tid + 128 * j;
      int r = cc >> 3, col = (cc & 7) << 2;
      cp_async16(sA32 + (r * 32 + col) * 4, Ab + (long long)(m0 + r) * lda + col);
      cp_async16(sB32 + (r * 32 + col) * 4, Bb + (long long)(n0 + r) * ldb + col);
    }
    cp_commit();
  }

  for (int it = 0; it < iters; it++) {
    const int s = it & 1;
    cp_wait0();
    __syncthreads();
    // convert f32 stage s -> bf16 hi/lo tiles
    const float* cA = sA + s * 2048;
    const float* cB = sB + s * 2048;
#pragma unroll
    for (int j = 0; j < 4; j++) {
      int e4 = tid + 128 * j;                  // float4 index 0..511
      float4 va = ((const float4*)cA)[e4];
      float4 vb = ((const float4*)cB)[e4];
      int e = e4 << 2;
      int r = e >> 5, cpos = e & 31;
      int off = r * GSTR + cpos;
      __nv_bfloat16 h0 = __float2bfloat16(va.x), h1 = __float2bfloat16(va.y);
      __nv_bfloat16 h2 = __float2bfloat16(va.z), h3 = __float2bfloat16(va.w);
      *(__nv_bfloat162*)(aHi + off)     = __nv_bfloat162(h0, h1);
      *(__nv_bfloat162*)(aHi + off + 2) = __nv_bfloat162(h2, h3);
      *(__nv_bfloat162*)(aLo + off) = __nv_bfloat162(
          __float2bfloat16(va.x - __bfloat162float(h0)),
          __float2bfloat16(va.y - __bfloat162float(h1)));
      *(__nv_bfloat162*)(aLo + off + 2) = __nv_bfloat162(
          __float2bfloat16(va.z - __bfloat162float(h2)),
          __float2bfloat16(va.w - __bfloat162float(h3)));
      __nv_bfloat16 g0 = __float2bfloat16(vb.x), g1 = __float2bfloat16(vb.y);
      __nv_bfloat16 g2 = __float2bfloat16(vb.z), g3 = __float2bfloat16(vb.w);
      *(__nv_bfloat162*)(bHi + off)     = __nv_bfloat162(g0, g1);
      *(__nv_bfloat162*)(bHi + off + 2) = __nv_bfloat162(g2, g3);
      *(__nv_bfloat162*)(bLo + off) = __nv_bfloat162(
          __float2bfloat16(vb.x - __bfloat162float(g0)),
          __float2bfloat16(vb.y - __bfloat162float(g1)));
      *(__nv_bfloat162*)(bLo + off + 2) = __nv_bfloat162(
          __float2bfloat16(vb.z - __bfloat162float(g2)),
          __float2bfloat16(vb.w - __bfloat162float(g3)));
    }
    // prefetch next stage while we compute
    if (it + 1 < iters) {
      int k0 = (it + 1) << 5;
      uint32_t so = (uint32_t)((s ^ 1) * 2048 * 4);
#pragma unroll
      for (int j = 0; j < 4; j++) {
        int cc = tid + 128 * j;
        int r = cc >> 3, col = (cc & 7) << 2;
        cp_async16(sA32 + so + (r * 32 + col) * 4, Ab + (long long)(m0 + r) * lda + k0 + col);
        cp_async16(sB32 + so + (r * 32 + col) * 4, Bb + (long long)(n0 + r) * ldb + k0 + col);
      }
      cp_commit();
    }
    __syncthreads();
    // 3 passes: hi*hi, hi*lo, lo*hi
#pragma unroll
    for (int p = 0; p < 3; p++) {
      uint32_t aBase = (p < 2) ? aHiB : aLoB;
      uint32_t bBase = (p == 1) ? bLoB : bHiB;
#pragma unroll
      for (int ks = 0; ks < 32; ks += 16) {
        uint32_t af[2][4], bf[2][4];
#pragma unroll
        for (int mi = 0; mi < 2; mi++) {
          uint32_t ad = aBase + (uint32_t)(((wm * 32 + mi * 16 + a_r) * GSTR + ks + a_c) * 2);
          ldm_x4(af[mi], ad);
        }
#pragma unroll
        for (int bo = 0; bo < 2; bo++) {
          uint32_t bd = bBase + (uint32_t)(((wn * 32 + bo * 16 + b_r) * GSTR + ks + b_c) * 2);
          ldm_x4(bf[bo], bd);
        }
#pragma unroll
        for (int mi = 0; mi < 2; mi++)
#pragma unroll
          for (int ni = 0; ni < 4; ni++)
            mma16816(acc[mi][ni], af[mi], bf[ni >> 1][(ni & 1) * 2], bf[ni >> 1][(ni & 1) * 2 + 1]);
      }
    }
  }

  // epilogue
  const int rb = lane >> 2, cb2 = (lane & 3) << 1;
#pragma unroll
  for (int mi = 0; mi < 2; mi++)
#pragma unroll
    for (int ni = 0; ni < 4; ni++) {
      int row = m0 + wm * 32 + mi * 16 + rb;
      int col = n0 + wn * 32 + ni * 8 + cb2;
      *(float2*)(Cb + (long long)row * ldc + col)       = make_float2(acc[mi][ni][0], acc[mi][ni][1]);
      *(float2*)(Cb + (long long)(row + 8) * ldc + col) = make_float2(acc[mi][ni][2], acc[mi][ni][3]);
    }
}

// ---------------- fused ane-norm + RoPE ----------------
// src: [row][head] packed rows of D; dst1: [head][row][D]; optional dst2 with row-dim NR2
__global__ void __launch_bounds__(128) norm_rope(
    const float* __restrict__ src, const float* __restrict__ w,
    const float* __restrict__ cs, const float* __restrict__ sn,
    float* __restrict__ dst, int NH, int NR,
    float* __restrict__ dst2, int NR2) {
  int r = blockIdx.x * 4 + (threadIdx.x >> 5);
  int lane = threadIdx.x & 31;
  int row = r / NH, h = r - row * NH;
  float4 v = ((const float4*)(src + (size_t)r * D_))[lane];
  float s = v.x + v.y + v.z + v.w;
#pragma unroll
  for (int o = 16; o; o >>= 1) s += __shfl_xor_sync(0xffffffffu, s, o);
  float mean = s * (1.0f / D_);
  float4 c = make_float4(v.x - mean, v.y - mean, v.z - mean, v.w - mean);
  float q2 = c.x * c.x + c.y * c.y + c.z * c.z + c.w * c.w;
#pragma unroll
  for (int o = 16; o; o >>= 1) q2 += __shfl_xor_sync(0xffffffffu, q2, o);
  float inv = rsqrtf(q2 * (1.0f / D_) + EPS_);
  float4 wv = ((const float4*)w)[lane];
  float4 n = make_float4(c.x * inv * wv.x, c.y * inv * wv.y,
                         c.z * inv * wv.z, c.w * inv * wv.w);
  float4 p;
  p.x = __shfl_xor_sync(0xffffffffu, n.x, 16);
  p.y = __shfl_xor_sync(0xffffffffu, n.y, 16);
  p.z = __shfl_xor_sync(0xffffffffu, n.z, 16);
  p.w = __shfl_xor_sync(0xffffffffu, n.w, 16);
  float sg = (lane < 16) ? -1.0f : 1.0f;
  float4 co = ((const float4*)(cs + (size_t)row * D_))[lane];
  float4 si = ((const float4*)(sn + (size_t)row * D_))[lane];
  float4 o;
  o.x = n.x * co.x + sg * p.x * si.x;
  o.y = n.y * co.y + sg * p.y * si.y;
  o.z = n.z * co.z + sg * p.z * si.z;
  o.w = n.w * co.w + sg * p.w * si.w;
  ((float4*)(dst + ((size_t)h * NR + row) * D_))[lane] = o;
  if (dst2) ((float4*)(dst2 + ((size_t)h * NR2 + row) * D_))[lane] = o;
}

// ---------------- v transpose (t,h,d) -> (h,t,d) ----------------
__global__ void __launch_bounds__(256) vtrans(
    const float* __restrict__ src, float* __restrict__ dst) {
  int i = blockIdx.x * 256 + threadIdx.x;
  int d4 = i & 31;
  int h = (i >> 5) & 7;
  int t = i >> 8;
  ((float4*)dst)[((size_t)h * T_ + t) * 32 + d4] = ((const float4*)src)[i];
}

// ---------------- copy cache_K -> kfull[:, 0:STATE, :] ----------------
__global__ void __launch_bounds__(256) copy_cacheK(
    const float* __restrict__ src, float* __restrict__ dst) {
  int i = blockIdx.x * 256 + threadIdx.x;     // float4 index over 8*3072*32
  const int PH = STATE_ * (D_ / 4);
  int h = i / PH, rem = i - h * PH;
  ((float4*)dst)[(size_t)h * S_ * (D_ / 4) + rem] = ((const float4*)src)[i];
}

// ---------------- transpose (h,s,d) -> (h,d,S) at s-offset so ----------------
__global__ void __launch_bounds__(256) transpose_hd(
    const float* __restrict__ src, float* __restrict__ dst, int ns, int so) {
  __shared__ float t[32][33];
  int h = blockIdx.z, d0 = blockIdx.y * 32, s0 = blockIdx.x * 32;
  int tx = threadIdx.x & 31, ty = threadIdx.x >> 5;   // 32x8
  const float* sp = src + ((size_t)h * ns + s0) * D_ + d0;
#pragma unroll
  for (int j = 0; j < 32; j += 8) t[ty + j][tx] = sp[(size_t)(ty + j) * D_ + tx];
  __syncthreads();
  float* dp = dst + ((size_t)h * D_ + d0) * S_ + so + s0;
#pragma unroll
  for (int j = 0; j < 32; j += 8) dp[(size_t)(ty + j) * S_ + tx] = t[tx][ty + j];
}

// ---------------- masked scaled softmax over S ----------------
__global__ void __launch_bounds__(256) softmax_mask(float* __restrict__ Sc) {
  const int rid = blockIdx.x;
  const int l = rid & (L_ - 1);
  const int allowed = STATE_ + CTX_ + l + 1;
  float* row = Sc + (size_t)rid * S_;
  const int t = threadIdx.x;
  float v[16];
  float mx = -INFINITY;
#pragma unroll
  for (int i = 0; i < 16; i++) {
    int idx = t + 256 * i;
    float x = (idx < allowed) ? row[idx] * SCALE_ : -INFINITY;
    v[i] = x;
    mx = fmaxf(mx, x);
  }
  __shared__ float red[8];
  int lane = t & 31, wid = t >> 5;
#pragma unroll
  for (int o = 16; o; o >>= 1) mx = fmaxf(mx, __shfl_xor_sync(0xffffffffu, mx, o));
  if (lane == 0) red[wid] = mx;
  __syncthreads();
  mx = red[0];
#pragma unroll
  for (int wi = 1; wi < 8; wi++) mx = fmaxf(mx, red[wi]);
  __syncthreads();
  float sum = 0.f;
#pragma unroll
  for (int i = 0; i < 16; i++) {
    float e = (v[i] > -INFINITY) ? __expf(v[i] - mx) : 0.f;
    v[i] = e;
    sum += e;
  }
#pragma unroll
  for (int o = 16; o; o >>= 1) sum += __shfl_xor_sync(0xffffffffu, sum, o);
  if (lane == 0) red[wid] = sum;
  __syncthreads();
  sum = red[0] + red[1] + red[2] + red[3] + red[4] + red[5] + red[6] + red[7];
  float inv = 1.f / sum;
#pragma unroll
  for (int i = 0; i < 16; i++) row[t + 256 * i] = v[i] * inv;
}

// ---------------- host launcher ----------------
extern "C" void kernel_launch(void* const* d_in, const int* in_sizes, int n_in,
                              void* d_out, int out_size) {
  const float* x    = (const float*)d_in[0];
  const float* xctx = (const float*)d_in[1];
  const float* cosq = (const float*)d_in[2];
  const float* sinq = (const float*)d_in[3];
  const float* cosk = (const float*)d_in[4];
  const float* sink = (const float*)d_in[5];
  const float* cK   = (const float*)d_in[6];
  const float* cV   = (const float*)d_in[7];
  // d_in[8] = causal_mask (bool) -- handled analytically
  const float* Wq   = (const float*)d_in[9];
  const float* Wk   = (const float*)d_in[10];
  const float* Wv   = (const float*)d_in[11];
  const float* Wo   = (const float*)d_in[12];
  const float* qw   = (const float*)d_in[13];
  const float* kw   = (const float*)d_in[14];

  float* out   = (float*)d_out;
  float* k_out = out + (size_t)L_ * HID_;                 // (HKV, T, D)
  float* v_out = k_out + (size_t)HKV_ * T_ * D_;          // (HKV, T, D)

  float *pc, *pq, *pqf, *pkraw, *pvraw, *pkfull, *pvt, *psc, *po;
  cudaGetSymbolAddress((void**)&pc, g_c);
  cudaGetSymbolAddress((void**)&pq, g_q);
  cudaGetSymbolAddress((void**)&pqf, g_qf);
  cudaGetSymbolAddress((void**)&pkraw, g_kraw);
  cudaGetSymbolAddress((void**)&pvraw, g_vraw);
  cudaGetSymbolAddress((void**)&pkfull, g_kfull);
  cudaGetSymbolAddress((void**)&pvt, g_vt);
  cudaGetSymbolAddress((void**)&psc, g_scores);
  cudaGetSymbolAddress((void**)&po, g_o);

  cudaFuncSetAttribute(gemm_split, cudaFuncAttributeMaxDynamicSharedMemorySize, SMEM_BYTES);

  // 1. c = [x_ctx; x]
  concat_c<<<T_ * HID_ / 4 / 256, 256>>>(xctx, x, pc);

  // 2. projections (tensor-core split GEMM)
  gemm_split<<<dim3(HID_ / 64, L_ / 64, 1), 128, SMEM_BYTES>>>(
      x, HID_, 0, Wq, HID_, 0, 0, pq, HID_, 0, HID_);
  gemm_split<<<dim3(HKV_ * D_ / 64, T_ / 64, 1), 128, SMEM_BYTES>>>(
      pc, HID_, 0, Wk, HID_, 0, 0, pkraw, HKV_ * D_, 0, HID_);
  gemm_split<<<dim3(HKV_ * D_ / 64, T_ / 64, 1), 128, SMEM_BYTES>>>(
      pc, HID_, 0, Wv, HID_, 0, 0, pvraw, HKV_ * D_, 0, HID_);

  // 3. norm + rope (+ write K into kfull new region), v transpose to (h,t,d)
  norm_rope<<<(L_ * HQ_) / 4, 128>>>(pq, qw, cosq, sinq, pqf, HQ_, L_, nullptr, 0);
  norm_rope<<<(T_ * HKV_) / 4, 128>>>(pkraw, kw, cosk, sink, k_out, HKV_, T_,
                                      pkfull + (size_t)STATE_ * D_, S_);
  vtrans<<<T_ * HKV_ * D_ / 4 / 256, 256>>>(pvraw, v_out);

  // 4. assemble full K / V^T
  copy_cacheK<<<HKV_ * STATE_ * (D_ / 4) / 256, 256>>>(cK, pkfull);
  transpose_hd<<<dim3(STATE_ / 32, D_ / 32, HKV_), 256>>>(cV, pvt, STATE_, 0);
  transpose_hd<<<dim3(T_ / 32, D_ / 32, HKV_), 256>>>(v_out, pvt, T_, STATE_);

  // 5. attention
  gemm_split<<<dim3(S_ / 64, L_ / 64, HQ_), 128, SMEM_BYTES>>>(
      pqf, D_, (long long)L_ * D_,
      pkfull, D_, (long long)S_ * D_, 2,
      psc, S_, (long long)L_ * S_, D_);
  softmax_mask<<<HQ_ * L_, 256>>>(psc);
  gemm_split<<<dim3(D_ / 64, L_ / 64, HQ_), 128, SMEM_BYTES>>>(
      psc, S_, (long long)L_ * S_,
      pvt, S_, (long long)D_ * S_, 2,
      po, HQ_ * D_, (long long)D_, S_);

  // 6. output projection
  gemm_split<<<dim3(HID_ / 64, L_ / 64, 1), 128, SMEM_BYTES>>>(
      po, HQ_ * D_, 0, Wo, HQ_ * D_, 0, 0, out, HID_, 0, HQ_ * D_);

  (void)in_sizes; (void)n_in; (void)out_size;
}

// round 3
// speedup vs baseline: 3.6170x; 1.8440x over previous
#include <cuda_runtime.h>
#include <cuda_bf16.h>
#include <math.h>
#include <stdint.h>

// Problem constants
#define L_     128
#define CTX_   896
#define T_     1024
#define STATE_ 3072
#define S_     4096
#define HID_   4096
#define HQ_    32
#define HKV_   8
#define D_     128
#define EPS_   1e-6f
#define SCALE_ 0.08838834764831845f   // 128^-0.5

// GEMM tiling
#define BM 128
#define BN 64
#define BK 32
#define GSTR 40                        // bf16 smem row stride in halves (80B)
#define STAGE_HALVES ((BM*2 + BN*2) * GSTR)          // aHi,aLo,bHi,bLo
#define GEMM_SMEM (2 * STAGE_HALVES * 2)             // 2 stages, bytes = 61440

// ---------------- device scratch ----------------
__device__ float g_c[T_ * HID_];                 // concat(x_ctx, x)
__device__ float g_q[L_ * HQ_ * D_];             // raw q projection
__device__ float g_qf[HQ_ * L_ * D_];            // normed+roped q (H,L,D)
__device__ float g_kraw[T_ * HKV_ * D_];         // raw k projection
__device__ float g_vraw[T_ * HKV_ * D_];         // raw v projection
__device__ float g_kfull[HKV_ * S_ * D_];        // full K (cache+new) (H,S,D)
__device__ float g_vt[HKV_ * D_ * S_];           // full V transposed (H,D,S)
__device__ float g_scores[(size_t)HQ_ * L_ * S_];// scores / probs
__device__ float g_o[L_ * HQ_ * D_];             // attention output (L, HQ*D)
__device__ float g_part[4 * 1024 * 1024];        // split-K partials (16MB)

// ---------------- helpers ----------------
__device__ __forceinline__ void ldm_x4(uint32_t (&r)[4], uint32_t addr) {
  asm volatile("ldmatrix.sync.aligned.m8n8.x4.shared.b16 {%0,%1,%2,%3}, [%4];\n"
    : "=r"(r[0]), "=r"(r[1]), "=r"(r[2]), "=r"(r[3]) : "r"(addr));
}
__device__ __forceinline__ void mma16816(float (&d)[4], const uint32_t (&a)[4],
                                         uint32_t b0, uint32_t b1) {
  asm volatile("mma.sync.aligned.m16n8k16.row.col.f32.bf16.bf16.f32 "
    "{%0,%1,%2,%3},{%4,%5,%6,%7},{%8,%9},{%0,%1,%2,%3};\n"
    : "+f"(d[0]), "+f"(d[1]), "+f"(d[2]), "+f"(d[3])
    : "r"(a[0]), "r"(a[1]), "r"(a[2]), "r"(a[3]), "r"(b0), "r"(b1));
}

// ---------------- concat c = [x_ctx; x] ----------------
__global__ void __launch_bounds__(256) concat_c(
    const float* __restrict__ xc, const float* __restrict__ x, float* __restrict__ c) {
  int i = blockIdx.x * 256 + threadIdx.x;
  const int CV = CTX_ * HID_ / 4;
  float4 v = (i < CV) ? ((const float4*)xc)[i] : ((const float4*)x)[i - CV];
  ((float4*)c)[i] = v;
}

// ============ batched split-bf16 tensor-core GEMM with split-K ============
// z = b*KS + ks.  C[b][M][N] (+=slices) = A[b][M][K] * B[b>>bshift][N][K]^T
// KS==1: write C + b*batchC (ldc).  KS>1: write C + z*batchC (dense, ldc=N).
__global__ void __launch_bounds__(256) gemm3(
    const float* __restrict__ A, int lda, long long batchA,
    const float* __restrict__ B, int ldb, long long batchB, int bshift,
    float* __restrict__ C, int ldc, long long batchC,
    int K, int KS)
{
  extern __shared__ __nv_bfloat16 sm[];
  const int tid = threadIdx.x, lane = tid & 31, wid = tid >> 5;
  const int wm = wid & 3, wn = wid >> 2;     // 4x2 warps, warp tile 32x32
  const int m0 = blockIdx.y * BM, n0 = blockIdx.x * BN;
  const int b = blockIdx.z / KS, ks = blockIdx.z - b * KS;
  const int Kc = K / KS, kbase = ks * Kc, iters = Kc / BK;

  const float* Ag = A + (long long)b * batchA + (size_t)(m0 + (tid >> 3)) * lda + kbase + ((tid & 7) << 2);
  const float* Bg = B + (long long)(b >> bshift) * batchB + (size_t)(n0 + (tid >> 3)) * ldb + kbase + ((tid & 7) << 2);

  float acc[2][4][4];
#pragma unroll
  for (int i = 0; i < 2; i++)
#pragma unroll
    for (int j = 0; j < 4; j++)
#pragma unroll
      for (int q = 0; q < 4; q++) acc[i][j][q] = 0.f;

  const uint32_t smB = (uint32_t)__cvta_generic_to_shared(sm);
  // stage base offsets (halves)
  const int aHiOff = 0, aLoOff = BM * GSTR, bHiOff = 2 * BM * GSTR, bLoOff = 2 * BM * GSTR + BN * GSTR;

  // ldmatrix lane addressing
  const int a_r = lane & 15, a_c = (lane & 16) >> 1;
  const int b_r = (lane & 7) | ((lane & 16) >> 1), b_c = lane & 8;

  float4 ra[4], rb[2];
  const int lrow = tid >> 3, lcol = (tid & 7) << 2;

  // prologue: load iter0, convert to stage0
#pragma unroll
  for (int j = 0; j < 4; j++) ra[j] = *(const float4*)(Ag + (size_t)(32 * j) * lda);
#pragma unroll
  for (int j = 0; j < 2; j++) rb[j] = *(const float4*)(Bg + (size_t)(32 * j) * ldb);

  for (int it = 0; it < iters; it++) {
    const int s = it & 1;
    __nv_bfloat16* st = sm + s * STAGE_HALVES;
    // convert current regs -> stage s
#pragma unroll
    for (int j = 0; j < 4; j++) {
      int off = (lrow + 32 * j) * GSTR + lcol;
      float4 v = ra[j];
      __nv_bfloat16 h0 = __float2bfloat16(v.x), h1 = __float2bfloat16(v.y);
      __nv_bfloat16 h2 = __float2bfloat16(v.z), h3 = __float2bfloat16(v.w);
      *(__nv_bfloat162*)(st + aHiOff + off)     = __nv_bfloat162(h0, h1);
      *(__nv_bfloat162*)(st + aHiOff + off + 2) = __nv_bfloat162(h2, h3);
      *(__nv_bfloat162*)(st + aLoOff + off) = __nv_bfloat162(
          __float2bfloat16(v.x - __bfloat162float(h0)),
          __float2bfloat16(v.y - __bfloat162float(h1)));
      *(__nv_bfloat162*)(st + aLoOff + off + 2) = __nv_bfloat162(
          __float2bfloat16(v.z - __bfloat162float(h2)),
          __float2bfloat16(v.w - __bfloat162float(h3)));
    }
#pragma unroll
    for (int j = 0; j < 2; j++) {
      int off = (lrow + 32 * j) * GSTR + lcol;
      float4 v = rb[j];
      __nv_bfloat16 h0 = __float2bfloat16(v.x), h1 = __float2bfloat16(v.y);
      __nv_bfloat16 h2 = __float2bfloat16(v.z), h3 = __float2bfloat16(v.w);
      *(__nv_bfloat162*)(st + bHiOff + off)     = __nv_bfloat162(h0, h1);
      *(__nv_bfloat162*)(st + bHiOff + off + 2) = __nv_bfloat162(h2, h3);
      *(__nv_bfloat162*)(st + bLoOff + off) = __nv_bfloat162(
          __float2bfloat16(v.x - __bfloat162float(h0)),
          __float2bfloat16(v.y - __bfloat162float(h1)));
      *(__nv_bfloat162*)(st + bLoOff + off + 2) = __nv_bfloat162(
          __float2bfloat16(v.z - __bfloat162float(h2)),
          __float2bfloat16(v.w - __bfloat162float(h3)));
    }
    __syncthreads();
    // prefetch next iter into regs (overlaps MMA below)
    if (it + 1 < iters) {
      const float* An = Ag + (it + 1) * BK;
      const float* Bn = Bg + (it + 1) * BK;
#pragma unroll
      for (int j = 0; j < 4; j++) ra[j] = *(const float4*)(An + (size_t)(32 * j) * lda);
#pragma unroll
      for (int j = 0; j < 2; j++) rb[j] = *(const float4*)(Bn + (size_t)(32 * j) * ldb);
    }
    // MMA on stage s
    uint32_t sb = smB + s * STAGE_HALVES * 2;
#pragma unroll
    for (int k16 = 0; k16 < BK; k16 += 16) {
      uint32_t aH[2][4], aL[2][4], bH[2][4], bL[2][4];
#pragma unroll
      for (int mi = 0; mi < 2; mi++) {
        uint32_t ro = (uint32_t)(((wm * 32 + mi * 16 + a_r) * GSTR + k16 + a_c) * 2);
        ldm_x4(aH[mi], sb + aHiOff * 2 + ro);
        ldm_x4(aL[mi], sb + aLoOff * 2 + ro);
      }
#pragma unroll
      for (int bo = 0; bo < 2; bo++) {
        uint32_t ro = (uint32_t)(((wn * 32 + bo * 16 + b_r) * GSTR + k16 + b_c) * 2);
        ldm_x4(bH[bo], sb + bHiOff * 2 + ro);
        ldm_x4(bL[bo], sb + bLoOff * 2 + ro);
      }
#pragma unroll
      for (int mi = 0; mi < 2; mi++)
#pragma unroll
        for (int ni = 0; ni < 4; ni++) {
          int g = ni >> 1, rr = (ni & 1) * 2;
          mma16816(acc[mi][ni], aH[mi], bH[g][rr], bH[g][rr + 1]);
          mma16816(acc[mi][ni], aH[mi], bL[g][rr], bL[g][rr + 1]);
          mma16816(acc[mi][ni], aL[mi], bH[g][rr], bH[g][rr + 1]);
        }
    }
    __syncthreads();
  }

  // epilogue
  float* Cb = (KS == 1) ? C + (long long)b * batchC : C + (long long)blockIdx.z * batchC;
  const int rb8 = lane >> 2, cb2 = (lane & 3) << 1;
#pragma unroll
  for (int mi = 0; mi < 2; mi++)
#pragma unroll
    for (int ni = 0; ni < 4; ni++) {
      int row = m0 + wm * 32 + mi * 16 + rb8;
      int col = n0 + wn * 32 + ni * 8 + cb2;
      *(float2*)(Cb + (long long)row * ldc + col)       = make_float2(acc[mi][ni][0], acc[mi][ni][1]);
      *(float2*)(Cb + (long long)(row + 8) * ldc + col) = make_float2(acc[mi][ni][2], acc[mi][ni][3]);
    }
}

// ---------------- split-K reduction ----------------
__global__ void __launch_bounds__(256) reduce_ks(
    const float* __restrict__ Pt, float* __restrict__ out,
    int ldc, long long batchC, int M, int N, int KS) {
  long long i4 = (long long)blockIdx.x * 256 + threadIdx.x;
  int perB = M * (N >> 2);
  int b = (int)(i4 / perB);
  int rem = (int)(i4 - (long long)b * perB);
  int m = rem / (N >> 2), n4 = rem - m * (N >> 2);
  const float4* base = (const float4*)Pt + (long long)b * KS * perB + rem;
  float4 s = base[0];
  for (int k = 1; k < KS; k++) {
    float4 v = base[(long long)k * perB];
    s.x += v.x; s.y += v.y; s.z += v.z; s.w += v.w;
  }
  *(float4*)(out + (long long)b * batchC + (long long)m * ldc + (n4 << 2)) = s;
}

// ---------------- fused ane-norm + RoPE ----------------
__global__ void __launch_bounds__(128) norm_rope(
    const float* __restrict__ src, const float* __restrict__ w,
    const float* __restrict__ cs, const float* __restrict__ sn,
    float* __restrict__ dst, int NH, int NR,
    float* __restrict__ dst2, int NR2) {
  int r = blockIdx.x * 4 + (threadIdx.x >> 5);
  int lane = threadIdx.x & 31;
  int row = r / NH, h = r - row * NH;
  float4 v = ((const float4*)(src + (size_t)r * D_))[lane];
  float s = v.x + v.y + v.z + v.w;
#pragma unroll
  for (int o = 16; o; o >>= 1) s += __shfl_xor_sync(0xffffffffu, s, o);
  float mean = s * (1.0f / D_);
  float4 c = make_float4(v.x - mean, v.y - mean, v.z - mean, v.w - mean);
  float q2 = c.x * c.x + c.y * c.y + c.z * c.z + c.w * c.w;
#pragma unroll
  for (int o = 16; o; o >>= 1) q2 += __shfl_xor_sync(0xffffffffu, q2, o);
  float inv = rsqrtf(q2 * (1.0f / D_) + EPS_);
  float4 wv = ((const float4*)w)[lane];
  float4 n = make_float4(c.x * inv * wv.x, c.y * inv * wv.y,
                         c.z * inv * wv.z, c.w * inv * wv.w);
  float4 p;
  p.x = __shfl_xor_sync(0xffffffffu, n.x, 16);
  p.y = __shfl_xor_sync(0xffffffffu, n.y, 16);
  p.z = __shfl_xor_sync(0xffffffffu, n.z, 16);
  p.w = __shfl_xor_sync(0xffffffffu, n.w, 16);
  float sg = (lane < 16) ? -1.0f : 1.0f;
  float4 co = ((const float4*)(cs + (size_t)row * D_))[lane];
  float4 si = ((const float4*)(sn + (size_t)row * D_))[lane];
  float4 o;
  o.x = n.x * co.x + sg * p.x * si.x;
  o.y = n.y * co.y + sg * p.y * si.y;
  o.z = n.z * co.z + sg * p.z * si.z;
  o.w = n.w * co.w + sg * p.w * si.w;
  ((float4*)(dst + ((size_t)h * NR + row) * D_))[lane] = o;
  if (dst2) ((float4*)(dst2 + ((size_t)h * NR2 + row) * D_))[lane] = o;
}

// ---------------- v transpose (t,h,d) -> (h,t,d) ----------------
__global__ void __launch_bounds__(256) vtrans(
    const float* __restrict__ src, float* __restrict__ dst) {
  int i = blockIdx.x * 256 + threadIdx.x;
  int d4 = i & 31;
  int h = (i >> 5) & 7;
  int t = i >> 8;
  ((float4*)dst)[((size_t)h * T_ + t) * 32 + d4] = ((const float4*)src)[i];
}

// ---------------- copy cache_K -> kfull[:, 0:STATE, :] ----------------
__global__ void __launch_bounds__(256) copy_cacheK(
    const float* __restrict__ src, float* __restrict__ dst) {
  int i = blockIdx.x * 256 + threadIdx.x;
  const int PH = STATE_ * (D_ / 4);
  int h = i / PH, rem = i - h * PH;
  ((float4*)dst)[(size_t)h * S_ * (D_ / 4) + rem] = ((const float4*)src)[i];
}

// ---------------- transpose (h,s,d) -> (h,d,S) at s-offset so ----------------
__global__ void __launch_bounds__(256) transpose_hd(
    const float* __restrict__ src, float* __restrict__ dst, int ns, int so) {
  __shared__ float t[32][33];
  int h = blockIdx.z, d0 = blockIdx.y * 32, s0 = blockIdx.x * 32;
  int tx = threadIdx.x & 31, ty = threadIdx.x >> 5;
  const float* sp = src + ((size_t)h * ns + s0) * D_ + d0;
#pragma unroll
  for (int j = 0; j < 32; j += 8) t[ty + j][tx] = sp[(size_t)(ty + j) * D_ + tx];
  __syncthreads();
  float* dp = dst + ((size_t)h * D_ + d0) * S_ + so + s0;
#pragma unroll
  for (int j = 0; j < 32; j += 8) dp[(size_t)(ty + j) * S_ + tx] = t[tx][ty + j];
}

// ---------------- masked scaled softmax over S ----------------
__global__ void __launch_bounds__(256) softmax_mask(float* __restrict__ Sc) {
  const int rid = blockIdx.x;
  const int l = rid & (L_ - 1);
  const int allowed = STATE_ + CTX_ + l + 1;
  float* row = Sc + (size_t)rid * S_;
  const int t = threadIdx.x;
  float v[16];
  float mx = -INFINITY;
#pragma unroll
  for (int i = 0; i < 16; i++) {
    int idx = t + 256 * i;
    float x = (idx < allowed) ? row[idx] * SCALE_ : -INFINITY;
    v[i] = x;
    mx = fmaxf(mx, x);
  }
  __shared__ float red[8];
  int lane = t & 31, wid = t >> 5;
#pragma unroll
  for (int o = 16; o; o >>= 1) mx = fmaxf(mx, __shfl_xor_sync(0xffffffffu, mx, o));
  if (lane == 0) red[wid] = mx;
  __syncthreads();
  mx = red[0];
#pragma unroll
  for (int wi = 1; wi < 8; wi++) mx = fmaxf(mx, red[wi]);
  __syncthreads();
  float sum = 0.f;
#pragma unroll
  for (int i = 0; i < 16; i++) {
    float e = (v[i] > -INFINITY) ? __expf(v[i] - mx) : 0.f;
    v[i] = e;
    sum += e;
  }
#pragma unroll
  for (int o = 16; o; o >>= 1) sum += __shfl_xor_sync(0xffffffffu, sum, o);
  if (lane == 0) red[wid] = sum;
  __syncthreads();
  sum = red[0] + red[1] + red[2] + red[3] + red[4] + red[5] + red[6] + red[7];
  float inv = 1.f / sum;
#pragma unroll
  for (int i = 0; i < 16; i++) row[t + 256 * i] = v[i] * inv;
}

// ---------------- host launcher ----------------
extern "C" void kernel_launch(void* const* d_in, const int* in_sizes, int n_in,
                              void* d_out, int out_size) {
  const float* x    = (const float*)d_in[0];
  const float* xctx = (const float*)d_in[1];
  const float* cosq = (const float*)d_in[2];
  const float* sinq = (const float*)d_in[3];
  const float* cosk = (const float*)d_in[4];
  const float* sink = (const float*)d_in[5];
  const float* cK   = (const float*)d_in[6];
  const float* cV   = (const float*)d_in[7];
  const float* Wq   = (const float*)d_in[9];
  const float* Wk   = (const float*)d_in[10];
  const float* Wv   = (const float*)d_in[11];
  const float* Wo   = (const float*)d_in[12];
  const float* qw   = (const float*)d_in[13];
  const float* kw   = (const float*)d_in[14];

  float* out   = (float*)d_out;
  float* k_out = out + (size_t)L_ * HID_;
  float* v_out = k_out + (size_t)HKV_ * T_ * D_;

  float *pc, *pq, *pqf, *pkraw, *pvraw, *pkfull, *pvt, *psc, *po, *pt;
  cudaGetSymbolAddress((void**)&pc, g_c);
  cudaGetSymbolAddress((void**)&pq, g_q);
  cudaGetSymbolAddress((void**)&pqf, g_qf);
  cudaGetSymbolAddress((void**)&pkraw, g_kraw);
  cudaGetSymbolAddress((void**)&pvraw, g_vraw);
  cudaGetSymbolAddress((void**)&pkfull, g_kfull);
  cudaGetSymbolAddress((void**)&pvt, g_vt);
  cudaGetSymbolAddress((void**)&psc, g_scores);
  cudaGetSymbolAddress((void**)&po, g_o);
  cudaGetSymbolAddress((void**)&pt, g_part);

  cudaFuncSetAttribute(gemm3, cudaFuncAttributeMaxDynamicSharedMemorySize, GEMM_SMEM);

  // 1. c = [x_ctx; x]
  concat_c<<<T_ * HID_ / 4 / 256, 256>>>(xctx, x, pc);

  // 2. projections
  // Q: M=128,N=4096,K=4096, KS=8
  gemm3<<<dim3(HID_ / BN, 1, 8), 256, GEMM_SMEM>>>(
      x, HID_, 0, Wq, HID_, 0, 0, pt, HID_, (long long)L_ * HID_, HID_, 8);
  reduce_ks<<<L_ * HID_ / 4 / 256, 256>>>(pt, pq, HID_, 0, L_, HID_, 8);
  // K: M=1024,N=1024,K=4096, KS=2
  gemm3<<<dim3(HKV_ * D_ / BN, T_ / BM, 2), 256, GEMM_SMEM>>>(
      pc, HID_, 0, Wk, HID_, 0, 0, pt, HKV_ * D_, (long long)T_ * HKV_ * D_, HID_, 2);
  reduce_ks<<<T_ * HKV_ * D_ / 4 / 256, 256>>>(pt, pkraw, HKV_ * D_, 0, T_, HKV_ * D_, 2);
  // V
  gemm3<<<dim3(HKV_ * D_ / BN, T_ / BM, 2), 256, GEMM_SMEM>>>(
      pc, HID_, 0, Wv, HID_, 0, 0, pt, HKV_ * D_, (long long)T_ * HKV_ * D_, HID_, 2);
  reduce_ks<<<T_ * HKV_ * D_ / 4 / 256, 256>>>(pt, pvraw, HKV_ * D_, 0, T_, HKV_ * D_, 2);

  // 3. norm + rope, v transpose
  norm_rope<<<(L_ * HQ_) / 4, 128>>>(pq, qw, cosq, sinq, pqf, HQ_, L_, nullptr, 0);
  norm_rope<<<(T_ * HKV_) / 4, 128>>>(pkraw, kw, cosk, sink, k_out, HKV_, T_,
                                      pkfull + (size_t)STATE_ * D_, S_);
  vtrans<<<T_ * HKV_ * D_ / 4 / 256, 256>>>(pvraw, v_out);

  // 4. assemble full K / V^T
  copy_cacheK<<<HKV_ * STATE_ * (D_ / 4) / 256, 256>>>(cK, pkfull);
  transpose_hd<<<dim3(STATE_ / 32, D_ / 32, HKV_), 256>>>(cV, pvt, STATE_, 0);
  transpose_hd<<<dim3(T_ / 32, D_ / 32, HKV_), 256>>>(v_out, pvt, T_, STATE_);

  // 5. attention
  // scores: per head M=128,N=4096,K=128, KS=1
  gemm3<<<dim3(S_ / BN, 1, HQ_), 256, GEMM_SMEM>>>(
      pqf, D_, (long long)L_ * D_,
      pkfull, D_, (long long)S_ * D_, 2,
      psc, S_, (long long)L_ * S_, D_, 1);
  softmax_mask<<<HQ_ * L_, 256>>>(psc);
  // PV: per head M=128,N=128,K=4096, KS=8
  gemm3<<<dim3(D_ / BN, 1, HQ_ * 8), 256, GEMM_SMEM>>>(
      psc, S_, (long long)L_ * S_,
      pvt, S_, (long long)D_ * S_, 2,
      pt, D_, (long long)L_ * D_, S_, 8);
  reduce_ks<<<HQ_ * L_ * D_ / 4 / 256, 256>>>(pt, po, HQ_ * D_, D_, L_, D_, 8);

  // 6. output projection: M=128,N=4096,K=4096, KS=8
  gemm3<<<dim3(HID_ / BN, 1, 8), 256, GEMM_SMEM>>>(
      po, HQ_ * D_, 0, Wo, HQ_ * D_, 0, 0, pt, HID_, (long long)L_ * HID_, HQ_ * D_, 8);
  reduce_ks<<<L_ * HID_ / 4 / 256, 256>>>(pt, out, HID_, 0, L_, HID_, 8);

  (void)in_sizes; (void)n_in; (void)out_size;
}